// round 14
// baseline (speedup 1.0000x reference)
#include <cuda_runtime.h>
#include <cuda_bf16.h>
#include <cstdint>

// Problem constants
#define E_      4
#define B_      16384
#define STATE_  29
#define HID_    512

// ---------------- SMEM layout (float offsets), TM=64 rows/CTA ----------------
#define OFF_AH  0
#define OFF_AL  16384
#define OFF_XS  32768     // 64 x 33 (padded)  = 2112
#define OFF_W0  34880     // W0 [IN x 512]     (<=14848)
#define OFF_B0  49728     // 512
#define OFF_B1  50240     // 512
#define OFF_W2  50752     // 512 x NO (<=6656)
#define SMEM_FLOATS 57408 // 229632 bytes
#define HROW 520          // Hs overlays [0, 33280) after mainloop (A frags dead)
#define XROW 33

// ---------------- device scratch ----------------
__device__ uint32_t g_B[2][(size_t)E_ * 262144];              // 8 MB total
__device__ float g_legs_diff[(size_t)E_ * 4 * B_ * 4];        // (E, 4, B, 4)
__device__ float g_state_out[(size_t)E_ * B_ * STATE_];       // (E, B, 29)

// ---------------- helpers ----------------
__device__ __forceinline__ uint32_t packbf(float x, float y) {
    __nv_bfloat162 h = __floats2bfloat162_rn(x, y);
    return *reinterpret_cast<uint32_t*>(&h);
}
__device__ __forceinline__ float bfhi(float x) {
    return __bfloat162float(__float2bfloat16_rn(x));
}
__device__ __forceinline__ void mma16816(float* d, uint4 a, uint32_t b0, uint32_t b1) {
    asm volatile(
        "mma.sync.aligned.m16n8k16.row.col.f32.bf16.bf16.f32 "
        "{%0,%1,%2,%3}, {%4,%5,%6,%7}, {%8,%9}, {%0,%1,%2,%3};"
        : "+f"(d[0]), "+f"(d[1]), "+f"(d[2]), "+f"(d[3])
        : "r"(a.x), "r"(a.y), "r"(a.z), "r"(a.w), "r"(b0), "r"(b1));
}

// =======================================================================
// Prep: split W1 into bf16 hi/lo, pack in mma B-fragment register order.
// =======================================================================
__global__ void prep_kernel(const float* __restrict__ wl1, const float* __restrict__ wp1) {
    int idx = blockIdx.x * 256 + threadIdx.x;      // 524288 total
    int l   = idx & 31;
    int kc  = (idx >> 5) & 31;
    int nt  = (idx >> 10) & 63;
    int e   = (idx >> 16) & 3;
    int net = idx >> 18;
    const float* W = (net ? wp1 : wl1) + (size_t)e * 512 * 512;   // [k][n]
    int g = l >> 2, c = l & 3;
    int n  = nt * 8 + g;
    int k0 = kc * 16 + 2 * c;
    float w00 = W[(size_t)k0 * 512 + n];
    float w01 = W[(size_t)(k0 + 1) * 512 + n];
    float w10 = W[(size_t)(k0 + 8) * 512 + n];
    float w11 = W[(size_t)(k0 + 9) * 512 + n];
    float h00 = bfhi(w00), h01 = bfhi(w01), h10 = bfhi(w10), h11 = bfhi(w11);
    uint32_t* dst = g_B[net] + (size_t)e * 262144 + ((size_t)(nt * 32 + kc) * 32 + l) * 4;
    dst[0] = packbf(w00, w01);
    dst[1] = packbf(w10, w11);
    dst[2] = packbf(w00 - h00, w01 - h01);
    dst[3] = packbf(w10 - h10, w11 - h11);
}

// =======================================================================
// Fused MLP, TM=64 rows per CTA, 256 threads (8 warps).
// Mainloop has depth-2 register prefetch of B fragments to hide L2 latency
// (1 CTA/SM -> only 2 warps/SMSP; without prefetch each kc exposes ~234cyc).
// =======================================================================
template <int NET>
__global__ void __launch_bounds__(256, 1)
mlp_kernel(const float* __restrict__ state, const float* __restrict__ act,
           const float* __restrict__ w0, const float* __restrict__ b0v,
           const float* __restrict__ b1v, const float* __restrict__ w2,
           const float* __restrict__ b2v, const float* __restrict__ mu,
           const float* __restrict__ sigma, const float* __restrict__ mu_t,
           const float* __restrict__ sigma_t) {
    constexpr int IN = NET ? 29 : 6;
    extern __shared__ float smem[];
    uint32_t* AH = (uint32_t*)(smem + OFF_AH);
    uint32_t* AL = (uint32_t*)(smem + OFF_AL);
    float* Hs  = smem;                 // overlay, used after mainloop only
    float* Xs  = smem + OFF_XS;
    float* W0s = smem + OFF_W0;
    float* B0s = smem + OFF_B0;
    float* B1s = smem + OFF_B1;
    float* W2s = smem + OFF_W2;

    const int t = threadIdx.x, lane = t & 31, wid = t >> 5;
    const int e = blockIdx.y;
    const int row0 = blockIdx.x * 64;

    // ---- stage normalized inputs Xs [64 x 33] ----
    for (int q = t; q < 64 * IN; q += 256) {
        int r = q / IN, i = q % IN;
        float v;
        if (NET == 0) {
            int grow = row0 + r, j = grow >> 14, bb = grow & (B_ - 1);
            const float* st = state + ((size_t)e * B_ + bb) * STATE_;
            const float* ac = act + ((size_t)e * B_ + bb) * 8;
            if (i == 0)      v = st[13 + 2 * j];
            else if (i == 1) v = st[21 + 2 * j];
            else if (i == 2) v = st[14 + 2 * j];
            else if (i == 3) v = st[22 + 2 * j];
            else if (i == 4) v = ac[2 * j];
            else             v = ac[2 * j + 1];
        } else {
            int bb = row0 + r;
            if (i < 13) v = state[((size_t)e * B_ + bb) * STATE_ + i];
            else {
                int m = i - 13, j, comp;
                if (m < 8) { j = m >> 1; comp = (m & 1) ? 2 : 0; }
                else       { int m2 = m - 8; j = m2 >> 1; comp = (m2 & 1) ? 3 : 1; }
                v = g_legs_diff[((size_t)e * 4 * B_ + (size_t)j * B_ + bb) * 4 + comp];
            }
        }
        Xs[r * XROW + i] = (v - mu[i]) / (sigma[i] + 1e-8f);
    }
    // ---- stage W0 [IN x 512], biases, packed W2 ----
    for (int q = t; q < IN * 512; q += 256) W0s[q] = w0[(size_t)e * IN * 512 + q];
    for (int q = t; q < 512; q += 256) {
        B0s[q] = b0v[(size_t)e * 512 + q];
        B1s[q] = b1v[(size_t)e * 512 + q];
    }
    if (NET == 0) {
        for (int q = t; q < 512 * 4; q += 256) {
            int k = q >> 2, o = q & 3;
            W2s[q] = w2[((size_t)e * 512 + k) * 8 + o];
        }
    } else {
        for (int q = t; q < 512 * 13; q += 256) {
            int k = q / 13, o = q % 13;
            W2s[q] = w2[((size_t)e * 512 + k) * 26 + o];
        }
    }
    __syncthreads();

    // ---- layer0: H[row][k] = relu(X*W0 + b0) written as A fragments ----
    {
        const int row = t & 63;
        const int q = t >> 6;
        const int mt = row >> 4, rr = row & 15;
        const int g = rr & 7, rh = rr >> 3;
        float xv[IN];
#pragma unroll
        for (int i = 0; i < IN; i++) xv[i] = Xs[row * XROW + i];
#pragma unroll 4
        for (int p = 0; p < 64; p++) {
            const int col0 = p * 8 + 2 * q;
            const int kc = col0 >> 4;
            const int kh = (col0 >> 3) & 1;
            float h0 = B0s[col0], h1 = B0s[col0 + 1];
#pragma unroll
            for (int i = 0; i < IN; i++) {
                h0 += xv[i] * W0s[i * 512 + col0];
                h1 += xv[i] * W0s[i * 512 + col0 + 1];
            }
            h0 = fmaxf(h0, 0.f);
            h1 = fmaxf(h1, 0.f);
            float h0h = bfhi(h0), h1h = bfhi(h1);
            const int addr = kc * 512 + mt * 128 + (g * 4 + q) * 4 + kh * 2 + rh;
            AH[addr] = packbf(h0, h1);
            AL[addr] = packbf(h0 - h0h, h1 - h1h);
        }
    }
    __syncthreads();

    // ---- layer1: [64 x 512] = A * W1, 3x bf16 split, prefetch depth 2 ----
    float acc[4][8][4];
#pragma unroll
    for (int m = 0; m < 4; m++)
#pragma unroll
        for (int n = 0; n < 8; n++)
#pragma unroll
            for (int j = 0; j < 4; j++) acc[m][n][j] = 0.f;

    const uint4* Bw = (const uint4*)(g_B[NET] + (size_t)e * 262144) + (size_t)wid * 8 * 32 * 32;
    // B address for (kc, ntl): (ntl*32 + kc)*32 + lane
    uint4 p0 = Bw[(0 * 32 + 0) * 32 + lane];
    uint4 p1 = Bw[(1 * 32 + 0) * 32 + lane];

    for (int kc = 0; kc < 32; kc++) {
        uint4 ah[4], al[4];
#pragma unroll
        for (int mt = 0; mt < 4; mt++) {
            ah[mt] = ((const uint4*)(AH + kc * 512 + mt * 128))[lane];
            al[mt] = ((const uint4*)(AL + kc * 512 + mt * 128))[lane];
        }
#pragma unroll
        for (int ntl = 0; ntl < 8; ntl++) {
            uint4 vb = p0;
            p0 = p1;
            // prefetch (kc, ntl+2) with carry into kc+1
            {
                int nntl = ntl + 2, nkc = kc;
                if (nntl >= 8) { nntl -= 8; nkc = kc + 1; }
                if (nkc < 32) p1 = Bw[(nntl * 32 + nkc) * 32 + lane];
            }
#pragma unroll
            for (int mt = 0; mt < 4; mt++) mma16816(acc[mt][ntl], ah[mt], vb.x, vb.y);
#pragma unroll
            for (int mt = 0; mt < 4; mt++) mma16816(acc[mt][ntl], ah[mt], vb.z, vb.w);
#pragma unroll
            for (int mt = 0; mt < 4; mt++) mma16816(acc[mt][ntl], al[mt], vb.x, vb.y);
        }
    }
    __syncthreads();   // A frags dead; Hs overlay becomes safe

    // ---- epilogue: relu(D + b1) -> Hs ----
    {
        const int g = lane >> 2, c = lane & 3;
#pragma unroll
        for (int mt = 0; mt < 4; mt++) {
#pragma unroll
            for (int ntl = 0; ntl < 8; ntl++) {
                const int col = wid * 64 + ntl * 8 + 2 * c;
                const int r1 = mt * 16 + g, r2 = r1 + 8;
                float b0c = B1s[col], b1c = B1s[col + 1];
                float2 v1 = make_float2(fmaxf(acc[mt][ntl][0] + b0c, 0.f),
                                        fmaxf(acc[mt][ntl][1] + b1c, 0.f));
                float2 v2 = make_float2(fmaxf(acc[mt][ntl][2] + b0c, 0.f),
                                        fmaxf(acc[mt][ntl][3] + b1c, 0.f));
                *(float2*)&Hs[r1 * HROW + col] = v1;
                *(float2*)&Hs[r2 * HROW + col] = v2;
            }
        }
    }
    __syncthreads();

    // ---- layer2 + outputs ----
    if (NET == 0) {
        const int row = t >> 2, o = t & 3;
        float s = 0.f;
#pragma unroll 8
        for (int k = 0; k < 512; k++) s += Hs[row * HROW + k] * W2s[k * 4 + o];
        float v = s + b2v[(size_t)e * 8 + o];
        g_legs_diff[((size_t)e * 4 * B_ + row0 + row) * 4 + o] =
            v * (sigma_t[o] + 1e-8f) + mu_t[o];
    } else {
        const int row = t >> 2, q = t & 3;
        const int bb = row0 + row;
        float s[4];
        int no = 0;
        int ols[4];
        for (int o = q; o < 13; o += 4) ols[no++] = o;
#pragma unroll
        for (int m = 0; m < 4; m++) s[m] = 0.f;
#pragma unroll 4
        for (int k = 0; k < 512; k++) {
            float h = Hs[row * HROW + k];
#pragma unroll
            for (int m = 0; m < 4; m++)
                if (m < no) s[m] += h * W2s[k * 13 + ols[m]];
        }
        const float* st = state + ((size_t)e * B_ + bb) * STATE_;
        float* o = g_state_out + ((size_t)e * B_ + bb) * STATE_;
#pragma unroll
        for (int m = 0; m < 4; m++) {
            if (m < no) {
                int c = ols[m];
                float v = s[m] + b2v[(size_t)e * 26 + c];
                o[c] = v * (sigma_t[c] + 1e-8f) + mu_t[c] + st[c];
            }
        }
        // leg part of next_state (cols 13..28)
        if (t < 64) {
            int b2i = row0 + t;
            const float* st2 = state + ((size_t)e * B_ + b2i) * STATE_;
            float* o2 = g_state_out + ((size_t)e * B_ + b2i) * STATE_;
#pragma unroll
            for (int j = 0; j < 4; j++) {
                const float* d = g_legs_diff + ((size_t)e * 4 * B_ + (size_t)j * B_ + b2i) * 4;
                o2[13 + 2 * j] = st2[13 + 2 * j] + d[0];
                o2[14 + 2 * j] = st2[14 + 2 * j] + d[2];
                o2[21 + 2 * j] = st2[21 + 2 * j] + d[1];
                o2[22 + 2 * j] = st2[22 + 2 * j] + d[3];
            }
        }
    }
}

// =======================================================================
// Kernel: ensemble mean
// =======================================================================
__global__ void mean_kernel(float* __restrict__ out) {
    const size_t n4 = (size_t)B_ * STATE_ / 4;
    const float4* s0 = (const float4*)g_state_out;
    const float4* s1 = (const float4*)(g_state_out + (size_t)1 * B_ * STATE_);
    const float4* s2 = (const float4*)(g_state_out + (size_t)2 * B_ * STATE_);
    const float4* s3 = (const float4*)(g_state_out + (size_t)3 * B_ * STATE_);
    for (size_t i = blockIdx.x * blockDim.x + threadIdx.x; i < n4;
         i += (size_t)gridDim.x * blockDim.x) {
        float4 a = s0[i], b = s1[i], c = s2[i], d = s3[i];
        float4 r;
        r.x = 0.25f * (a.x + b.x + c.x + d.x);
        r.y = 0.25f * (a.y + b.y + c.y + d.y);
        r.z = 0.25f * (a.z + b.z + c.z + d.z);
        r.w = 0.25f * (a.w + b.w + c.w + d.w);
        ((float4*)out)[i] = r;
    }
}

extern "C" void kernel_launch(void* const* d_in, const int* in_sizes, int n_in,
                              void* d_out, int out_size) {
    const float* state       = (const float*)d_in[0];
    const float* act         = (const float*)d_in[1];
    const float* wl0         = (const float*)d_in[2];
    const float* bl0         = (const float*)d_in[3];
    const float* wl1         = (const float*)d_in[4];
    const float* bl1         = (const float*)d_in[5];
    const float* wl2         = (const float*)d_in[6];
    const float* bl2         = (const float*)d_in[7];
    const float* wp0         = (const float*)d_in[8];
    const float* bp0         = (const float*)d_in[9];
    const float* wp1         = (const float*)d_in[10];
    const float* bp1         = (const float*)d_in[11];
    const float* wp2         = (const float*)d_in[12];
    const float* bp2         = (const float*)d_in[13];
    const float* mu_leg      = (const float*)d_in[14];
    const float* sigma_leg   = (const float*)d_in[15];
    const float* mu_pose     = (const float*)d_in[16];
    const float* sigma_pose  = (const float*)d_in[17];
    const float* mu_t_leg    = (const float*)d_in[18];
    const float* sigma_t_leg = (const float*)d_in[19];
    const float* mu_t_pose   = (const float*)d_in[20];
    const float* sigma_t_pose= (const float*)d_in[21];

    const int smem = SMEM_FLOATS * (int)sizeof(float);   // 229632 B
    cudaFuncSetAttribute(mlp_kernel<0>, cudaFuncAttributeMaxDynamicSharedMemorySize, smem);
    cudaFuncSetAttribute(mlp_kernel<1>, cudaFuncAttributeMaxDynamicSharedMemorySize, smem);

    // 1) pack W1 fragments (bf16 hi/lo)
    prep_kernel<<<2048, 256>>>(wl1, wp1);

    // 2) leg net: (E, 4B) rows -> g_legs_diff
    mlp_kernel<0><<<dim3(1024, E_), 256, smem>>>(state, act, wl0, bl0, bl1, wl2, bl2,
                                                 mu_leg, sigma_leg, mu_t_leg, sigma_t_leg);

    // 3) pose net: (E, B) rows -> g_state_out
    mlp_kernel<1><<<dim3(256, E_), 256, smem>>>(state, nullptr, wp0, bp0, bp1, wp2, bp2,
                                                mu_pose, sigma_pose, mu_t_pose, sigma_t_pose);

    // 4) ensemble mean
    mean_kernel<<<256, 256>>>((float*)d_out);
}

// round 15
// speedup vs baseline: 1.5003x; 1.5003x over previous
#include <cuda_runtime.h>
#include <cuda_bf16.h>
#include <cstdint>

// Problem constants
#define E_      4
#define B_      16384
#define STATE_  29
#define HID_    512

// ---------------- SMEM layout (float offsets), TM=64 rows/CTA ----------------
#define OFF_AH  0
#define OFF_AL  16384
#define OFF_XS  32768     // 64 x 33 (padded)  = 2112
#define OFF_W0  34880     // W0 [IN x 512]     (<=14848)  -- overlaid by B ring in mainloop
#define OFF_BST 34880     // B cp.async ring: 4 slots x 256 thr x 16B = 4096 floats
#define OFF_DUM 38976     // dummy tail slot: 256 thr x 16B = 1024 floats
#define OFF_B0  49728     // 512
#define OFF_B1  50240     // 512
#define OFF_W2  50752     // 512 x NO (<=6656)
#define SMEM_FLOATS 57408 // 229632 bytes
#define HROW 520          // Hs overlays [0, 33280) after mainloop (A frags dead)
#define XROW 33

// ---------------- device scratch ----------------
__device__ uint32_t g_B[2][(size_t)E_ * 262144];              // 8 MB total
__device__ float g_legs_diff[(size_t)E_ * 4 * B_ * 4];        // (E, 4, B, 4)
__device__ float g_state_out[(size_t)E_ * B_ * STATE_];       // (E, B, 29)

// ---------------- helpers ----------------
__device__ __forceinline__ uint32_t packbf(float x, float y) {
    __nv_bfloat162 h = __floats2bfloat162_rn(x, y);
    return *reinterpret_cast<uint32_t*>(&h);
}
__device__ __forceinline__ float bfhi(float x) {
    return __bfloat162float(__float2bfloat16_rn(x));
}
__device__ __forceinline__ void mma16816(float* d, uint4 a, uint32_t b0, uint32_t b1) {
    asm volatile(
        "mma.sync.aligned.m16n8k16.row.col.f32.bf16.bf16.f32 "
        "{%0,%1,%2,%3}, {%4,%5,%6,%7}, {%8,%9}, {%0,%1,%2,%3};"
        : "+f"(d[0]), "+f"(d[1]), "+f"(d[2]), "+f"(d[3])
        : "r"(a.x), "r"(a.y), "r"(a.z), "r"(a.w), "r"(b0), "r"(b1));
}
__device__ __forceinline__ uint32_t smem_addr_u32(const void* p) {
    uint32_t a;
    asm("{ .reg .u64 t; cvta.to.shared.u64 t, %1; cvt.u32.u64 %0, t; }" : "=r"(a) : "l"(p));
    return a;
}
__device__ __forceinline__ void cpasync16(uint32_t dst, const void* src) {
    asm volatile("cp.async.cg.shared.global [%0], [%1], 16;" :: "r"(dst), "l"(src) : "memory");
}
#define CPCOMMIT() asm volatile("cp.async.commit_group;" ::: "memory")
#define CPWAIT2()  asm volatile("cp.async.wait_group 2;" ::: "memory")

// =======================================================================
// Prep: split W1 into bf16 hi/lo, pack in mma B-fragment register order.
// =======================================================================
__global__ void prep_kernel(const float* __restrict__ wl1, const float* __restrict__ wp1) {
    int idx = blockIdx.x * 256 + threadIdx.x;      // 524288 total
    int l   = idx & 31;
    int kc  = (idx >> 5) & 31;
    int nt  = (idx >> 10) & 63;
    int e   = (idx >> 16) & 3;
    int net = idx >> 18;
    const float* W = (net ? wp1 : wl1) + (size_t)e * 512 * 512;   // [k][n]
    int g = l >> 2, c = l & 3;
    int n  = nt * 8 + g;
    int k0 = kc * 16 + 2 * c;
    float w00 = W[(size_t)k0 * 512 + n];
    float w01 = W[(size_t)(k0 + 1) * 512 + n];
    float w10 = W[(size_t)(k0 + 8) * 512 + n];
    float w11 = W[(size_t)(k0 + 9) * 512 + n];
    float h00 = bfhi(w00), h01 = bfhi(w01), h10 = bfhi(w10), h11 = bfhi(w11);
    uint32_t* dst = g_B[net] + (size_t)e * 262144 + ((size_t)(nt * 32 + kc) * 32 + l) * 4;
    dst[0] = packbf(w00, w01);
    dst[1] = packbf(w10, w11);
    dst[2] = packbf(w00 - h00, w01 - h01);
    dst[3] = packbf(w10 - h10, w11 - h11);
}

// =======================================================================
// Fused MLP, TM=64 rows per CTA, 256 threads (8 warps).
// B fragments flow through a per-thread cp.async 4-slot SMEM ring
// (3 groups in flight) -> L2 latency hidden with zero register cost.
// =======================================================================
template <int NET>
__global__ void __launch_bounds__(256, 1)
mlp_kernel(const float* __restrict__ state, const float* __restrict__ act,
           const float* __restrict__ w0, const float* __restrict__ b0v,
           const float* __restrict__ b1v, const float* __restrict__ w2,
           const float* __restrict__ b2v, const float* __restrict__ mu,
           const float* __restrict__ sigma, const float* __restrict__ mu_t,
           const float* __restrict__ sigma_t) {
    constexpr int IN = NET ? 29 : 6;
    extern __shared__ float smem[];
    uint32_t* AH = (uint32_t*)(smem + OFF_AH);
    uint32_t* AL = (uint32_t*)(smem + OFF_AL);
    float* Hs  = smem;                 // overlay, used after mainloop only
    float* Xs  = smem + OFF_XS;
    float* W0s = smem + OFF_W0;
    float* B0s = smem + OFF_B0;
    float* B1s = smem + OFF_B1;
    float* W2s = smem + OFF_W2;

    const int t = threadIdx.x, lane = t & 31, wid = t >> 5;
    const int e = blockIdx.y;
    const int row0 = blockIdx.x * 64;

    // ---- stage normalized inputs Xs [64 x 33] ----
    for (int q = t; q < 64 * IN; q += 256) {
        int r = q / IN, i = q % IN;
        float v;
        if (NET == 0) {
            int grow = row0 + r, j = grow >> 14, bb = grow & (B_ - 1);
            const float* st = state + ((size_t)e * B_ + bb) * STATE_;
            const float* ac = act + ((size_t)e * B_ + bb) * 8;
            if (i == 0)      v = st[13 + 2 * j];
            else if (i == 1) v = st[21 + 2 * j];
            else if (i == 2) v = st[14 + 2 * j];
            else if (i == 3) v = st[22 + 2 * j];
            else if (i == 4) v = ac[2 * j];
            else             v = ac[2 * j + 1];
        } else {
            int bb = row0 + r;
            if (i < 13) v = state[((size_t)e * B_ + bb) * STATE_ + i];
            else {
                int m = i - 13, j, comp;
                if (m < 8) { j = m >> 1; comp = (m & 1) ? 2 : 0; }
                else       { int m2 = m - 8; j = m2 >> 1; comp = (m2 & 1) ? 3 : 1; }
                v = g_legs_diff[((size_t)e * 4 * B_ + (size_t)j * B_ + bb) * 4 + comp];
            }
        }
        Xs[r * XROW + i] = (v - mu[i]) / (sigma[i] + 1e-8f);
    }
    // ---- stage W0 [IN x 512], biases, packed W2 ----
    for (int q = t; q < IN * 512; q += 256) W0s[q] = w0[(size_t)e * IN * 512 + q];
    for (int q = t; q < 512; q += 256) {
        B0s[q] = b0v[(size_t)e * 512 + q];
        B1s[q] = b1v[(size_t)e * 512 + q];
    }
    if (NET == 0) {
        for (int q = t; q < 512 * 4; q += 256) {
            int k = q >> 2, o = q & 3;
            W2s[q] = w2[((size_t)e * 512 + k) * 8 + o];
        }
    } else {
        for (int q = t; q < 512 * 13; q += 256) {
            int k = q / 13, o = q % 13;
            W2s[q] = w2[((size_t)e * 512 + k) * 26 + o];
        }
    }
    __syncthreads();

    // ---- layer0: H[row][k] = relu(X*W0 + b0) written as A fragments ----
    {
        const int row = t & 63;
        const int q = t >> 6;
        const int mt = row >> 4, rr = row & 15;
        const int g = rr & 7, rh = rr >> 3;
        float xv[IN];
#pragma unroll
        for (int i = 0; i < IN; i++) xv[i] = Xs[row * XROW + i];
#pragma unroll 4
        for (int p = 0; p < 64; p++) {
            const int col0 = p * 8 + 2 * q;
            const int kc = col0 >> 4;
            const int kh = (col0 >> 3) & 1;
            float h0 = B0s[col0], h1 = B0s[col0 + 1];
#pragma unroll
            for (int i = 0; i < IN; i++) {
                h0 += xv[i] * W0s[i * 512 + col0];
                h1 += xv[i] * W0s[i * 512 + col0 + 1];
            }
            h0 = fmaxf(h0, 0.f);
            h1 = fmaxf(h1, 0.f);
            float h0h = bfhi(h0), h1h = bfhi(h1);
            const int addr = kc * 512 + mt * 128 + (g * 4 + q) * 4 + kh * 2 + rh;
            AH[addr] = packbf(h0, h1);
            AL[addr] = packbf(h0 - h0h, h1 - h1h);
        }
    }
    __syncthreads();   // layer0 done; W0s region now free for the B ring

    // ---- layer1: [64 x 512] = A * W1, 3x bf16 split, cp.async B ring ----
    float acc[4][8][4];
#pragma unroll
    for (int m = 0; m < 4; m++)
#pragma unroll
        for (int n = 0; n < 8; n++)
#pragma unroll
            for (int j = 0; j < 4; j++) acc[m][n][j] = 0.f;

    const uint4* Bw = (const uint4*)(g_B[NET] + (size_t)e * 262144) + (size_t)wid * 8 * 32 * 32;
    const uint4* Bring = (const uint4*)(smem + OFF_BST);          // [slot][256]
    const uint32_t ringAddr = smem_addr_u32(smem + OFF_BST);
    const uint32_t dumAddr  = smem_addr_u32(smem + OFF_DUM) + (uint32_t)t * 16;

    // stream index m = kc*8 + ntl; source uint4: Bw[((m&7)*32 + (m>>3))*32 + lane]
    // prologue: issue m = 0, 1, 2
#pragma unroll
    for (int m = 0; m < 3; m++) {
        cpasync16(ringAddr + ((m & 3) * 256 + t) * 16,
                  Bw + ((m & 7) * 32 + (m >> 3)) * 32 + lane);
        CPCOMMIT();
    }

    for (int kc = 0; kc < 32; kc++) {
        uint4 ah[4], al[4];
#pragma unroll
        for (int mt = 0; mt < 4; mt++) {
            ah[mt] = ((const uint4*)(AH + kc * 512 + mt * 128))[lane];
            al[mt] = ((const uint4*)(AL + kc * 512 + mt * 128))[lane];
        }
#pragma unroll
        for (int ntl = 0; ntl < 8; ntl++) {
            const int m = kc * 8 + ntl;
            CPWAIT2();                                   // group m complete
            uint4 vb = Bring[(m & 3) * 256 + t];
            // issue m+3 (or dummy at tail) -- predicated selects, no branch
            const int mn = m + 3;
            const bool real = (mn < 256);
            uint32_t dst = real ? ringAddr + ((mn & 3) * 256 + t) * 16 : dumAddr;
            const uint4* src = real ? Bw + ((mn & 7) * 32 + (mn >> 3)) * 32 + lane
                                    : Bw + lane;
            cpasync16(dst, src);
            CPCOMMIT();
#pragma unroll
            for (int mt = 0; mt < 4; mt++) mma16816(acc[mt][ntl], ah[mt], vb.x, vb.y);
#pragma unroll
            for (int mt = 0; mt < 4; mt++) mma16816(acc[mt][ntl], ah[mt], vb.z, vb.w);
#pragma unroll
            for (int mt = 0; mt < 4; mt++) mma16816(acc[mt][ntl], al[mt], vb.x, vb.y);
        }
    }
    asm volatile("cp.async.wait_all;" ::: "memory");
    __syncthreads();   // A frags dead; Hs overlay becomes safe

    // ---- epilogue: relu(D + b1) -> Hs ----
    {
        const int g = lane >> 2, c = lane & 3;
#pragma unroll
        for (int mt = 0; mt < 4; mt++) {
#pragma unroll
            for (int ntl = 0; ntl < 8; ntl++) {
                const int col = wid * 64 + ntl * 8 + 2 * c;
                const int r1 = mt * 16 + g, r2 = r1 + 8;
                float b0c = B1s[col], b1c = B1s[col + 1];
                float2 v1 = make_float2(fmaxf(acc[mt][ntl][0] + b0c, 0.f),
                                        fmaxf(acc[mt][ntl][1] + b1c, 0.f));
                float2 v2 = make_float2(fmaxf(acc[mt][ntl][2] + b0c, 0.f),
                                        fmaxf(acc[mt][ntl][3] + b1c, 0.f));
                *(float2*)&Hs[r1 * HROW + col] = v1;
                *(float2*)&Hs[r2 * HROW + col] = v2;
            }
        }
    }
    __syncthreads();

    // ---- layer2 + outputs ----
    if (NET == 0) {
        const int row = t >> 2, o = t & 3;
        float s = 0.f;
#pragma unroll 8
        for (int k = 0; k < 512; k++) s += Hs[row * HROW + k] * W2s[k * 4 + o];
        float v = s + b2v[(size_t)e * 8 + o];
        g_legs_diff[((size_t)e * 4 * B_ + row0 + row) * 4 + o] =
            v * (sigma_t[o] + 1e-8f) + mu_t[o];
    } else {
        const int row = t >> 2, q = t & 3;
        const int bb = row0 + row;
        float s[4];
        int no = 0;
        int ols[4];
        for (int o = q; o < 13; o += 4) ols[no++] = o;
#pragma unroll
        for (int m = 0; m < 4; m++) s[m] = 0.f;
#pragma unroll 4
        for (int k = 0; k < 512; k++) {
            float h = Hs[row * HROW + k];
#pragma unroll
            for (int m = 0; m < 4; m++)
                if (m < no) s[m] += h * W2s[k * 13 + ols[m]];
        }
        const float* st = state + ((size_t)e * B_ + bb) * STATE_;
        float* o = g_state_out + ((size_t)e * B_ + bb) * STATE_;
#pragma unroll
        for (int m = 0; m < 4; m++) {
            if (m < no) {
                int c = ols[m];
                float v = s[m] + b2v[(size_t)e * 26 + c];
                o[c] = v * (sigma_t[c] + 1e-8f) + mu_t[c] + st[c];
            }
        }
        // leg part of next_state (cols 13..28)
        if (t < 64) {
            int b2i = row0 + t;
            const float* st2 = state + ((size_t)e * B_ + b2i) * STATE_;
            float* o2 = g_state_out + ((size_t)e * B_ + b2i) * STATE_;
#pragma unroll
            for (int j = 0; j < 4; j++) {
                const float* d = g_legs_diff + ((size_t)e * 4 * B_ + (size_t)j * B_ + b2i) * 4;
                o2[13 + 2 * j] = st2[13 + 2 * j] + d[0];
                o2[14 + 2 * j] = st2[14 + 2 * j] + d[2];
                o2[21 + 2 * j] = st2[21 + 2 * j] + d[1];
                o2[22 + 2 * j] = st2[22 + 2 * j] + d[3];
            }
        }
    }
}

// =======================================================================
// Kernel: ensemble mean
// =======================================================================
__global__ void mean_kernel(float* __restrict__ out) {
    const size_t n4 = (size_t)B_ * STATE_ / 4;
    const float4* s0 = (const float4*)g_state_out;
    const float4* s1 = (const float4*)(g_state_out + (size_t)1 * B_ * STATE_);
    const float4* s2 = (const float4*)(g_state_out + (size_t)2 * B_ * STATE_);
    const float4* s3 = (const float4*)(g_state_out + (size_t)3 * B_ * STATE_);
    for (size_t i = blockIdx.x * blockDim.x + threadIdx.x; i < n4;
         i += (size_t)gridDim.x * blockDim.x) {
        float4 a = s0[i], b = s1[i], c = s2[i], d = s3[i];
        float4 r;
        r.x = 0.25f * (a.x + b.x + c.x + d.x);
        r.y = 0.25f * (a.y + b.y + c.y + d.y);
        r.z = 0.25f * (a.z + b.z + c.z + d.z);
        r.w = 0.25f * (a.w + b.w + c.w + d.w);
        ((float4*)out)[i] = r;
    }
}

extern "C" void kernel_launch(void* const* d_in, const int* in_sizes, int n_in,
                              void* d_out, int out_size) {
    const float* state       = (const float*)d_in[0];
    const float* act         = (const float*)d_in[1];
    const float* wl0         = (const float*)d_in[2];
    const float* bl0         = (const float*)d_in[3];
    const float* wl1         = (const float*)d_in[4];
    const float* bl1         = (const float*)d_in[5];
    const float* wl2         = (const float*)d_in[6];
    const float* bl2         = (const float*)d_in[7];
    const float* wp0         = (const float*)d_in[8];
    const float* bp0         = (const float*)d_in[9];
    const float* wp1         = (const float*)d_in[10];
    const float* bp1         = (const float*)d_in[11];
    const float* wp2         = (const float*)d_in[12];
    const float* bp2         = (const float*)d_in[13];
    const float* mu_leg      = (const float*)d_in[14];
    const float* sigma_leg   = (const float*)d_in[15];
    const float* mu_pose     = (const float*)d_in[16];
    const float* sigma_pose  = (const float*)d_in[17];
    const float* mu_t_leg    = (const float*)d_in[18];
    const float* sigma_t_leg = (const float*)d_in[19];
    const float* mu_t_pose   = (const float*)d_in[20];
    const float* sigma_t_pose= (const float*)d_in[21];

    const int smem = SMEM_FLOATS * (int)sizeof(float);   // 229632 B
    cudaFuncSetAttribute(mlp_kernel<0>, cudaFuncAttributeMaxDynamicSharedMemorySize, smem);
    cudaFuncSetAttribute(mlp_kernel<1>, cudaFuncAttributeMaxDynamicSharedMemorySize, smem);

    // 1) pack W1 fragments (bf16 hi/lo)
    prep_kernel<<<2048, 256>>>(wl1, wp1);

    // 2) leg net: (E, 4B) rows -> g_legs_diff
    mlp_kernel<0><<<dim3(1024, E_), 256, smem>>>(state, act, wl0, bl0, bl1, wl2, bl2,
                                                 mu_leg, sigma_leg, mu_t_leg, sigma_t_leg);

    // 3) pose net: (E, B) rows -> g_state_out
    mlp_kernel<1><<<dim3(256, E_), 256, smem>>>(state, nullptr, wp0, bp0, bp1, wp2, bp2,
                                                mu_pose, sigma_pose, mu_t_pose, sigma_t_pose);

    // 4) ensemble mean
    mean_kernel<<<256, 256>>>((float*)d_out);
}

// round 16
// speedup vs baseline: 1.6664x; 1.1107x over previous
#include <cuda_runtime.h>
#include <cuda_bf16.h>
#include <cstdint>

// Problem constants
#define E_      4
#define B_      16384
#define STATE_  29
#define HID_    512

// ---------------- SMEM layout (float offsets), TM=64 rows/CTA ----------------
#define OFF_AH  0
#define OFF_AL  16384
#define OFF_XS  32768     // 64 x 33 (padded)  = 2112   (dead after layer0 -> reused as Rbuf)
#define OFF_W0  34880     // W0 [IN x 512]     (<=14848)
#define OFF_B0  49728     // 512
#define OFF_B1  50240     // 512
#define OFF_W2  50752     // 512 x NO (<=6656)
#define SMEM_FLOATS 57408 // 229632 bytes
#define HROW 520          // Hs overlays [0, 33280) after mainloop (A frags dead)
#define XROW 33

#define NT 512            // threads per CTA (16 warps -> 4 warps/SMSP)

// ---------------- device scratch ----------------
__device__ uint32_t g_B[2][(size_t)E_ * 262144];              // 8 MB total
__device__ float g_legs_diff[(size_t)E_ * 4 * B_ * 4];        // (E, 4, B, 4)
__device__ float g_state_out[(size_t)E_ * B_ * STATE_];       // (E, B, 29)

// ---------------- helpers ----------------
__device__ __forceinline__ uint32_t packbf(float x, float y) {
    __nv_bfloat162 h = __floats2bfloat162_rn(x, y);
    return *reinterpret_cast<uint32_t*>(&h);
}
__device__ __forceinline__ float bfhi(float x) {
    return __bfloat162float(__float2bfloat16_rn(x));
}
__device__ __forceinline__ void mma16816(float* d, uint4 a, uint32_t b0, uint32_t b1) {
    asm volatile(
        "mma.sync.aligned.m16n8k16.row.col.f32.bf16.bf16.f32 "
        "{%0,%1,%2,%3}, {%4,%5,%6,%7}, {%8,%9}, {%0,%1,%2,%3};"
        : "+f"(d[0]), "+f"(d[1]), "+f"(d[2]), "+f"(d[3])
        : "r"(a.x), "r"(a.y), "r"(a.z), "r"(a.w), "r"(b0), "r"(b1));
}

// =======================================================================
// Prep: split W1 into bf16 hi/lo, pack in mma B-fragment register order.
// =======================================================================
__global__ void prep_kernel(const float* __restrict__ wl1, const float* __restrict__ wp1) {
    int idx = blockIdx.x * 256 + threadIdx.x;      // 524288 total
    int l   = idx & 31;
    int kc  = (idx >> 5) & 31;
    int nt  = (idx >> 10) & 63;
    int e   = (idx >> 16) & 3;
    int net = idx >> 18;
    const float* W = (net ? wp1 : wl1) + (size_t)e * 512 * 512;   // [k][n]
    int g = l >> 2, c = l & 3;
    int n  = nt * 8 + g;
    int k0 = kc * 16 + 2 * c;
    float w00 = W[(size_t)k0 * 512 + n];
    float w01 = W[(size_t)(k0 + 1) * 512 + n];
    float w10 = W[(size_t)(k0 + 8) * 512 + n];
    float w11 = W[(size_t)(k0 + 9) * 512 + n];
    float h00 = bfhi(w00), h01 = bfhi(w01), h10 = bfhi(w10), h11 = bfhi(w11);
    uint32_t* dst = g_B[net] + (size_t)e * 262144 + ((size_t)(nt * 32 + kc) * 32 + l) * 4;
    dst[0] = packbf(w00, w01);
    dst[1] = packbf(w10, w11);
    dst[2] = packbf(w00 - h00, w01 - h01);
    dst[3] = packbf(w10 - h10, w11 - h11);
}

// =======================================================================
// Fused MLP, TM=64 rows per CTA, 512 threads (16 warps -> 4 warps/SMSP).
// Warp (wm = wid&1, wn = wid>>1): rows wm*32..+31 (2 mtiles), n-cols
// wn*64..+63 (8 ntiles). acc[2][8][4] = 64 regs -> fits 512-thread RF.
// =======================================================================
template <int NET>
__global__ void __launch_bounds__(NT, 1)
mlp_kernel(const float* __restrict__ state, const float* __restrict__ act,
           const float* __restrict__ w0, const float* __restrict__ b0v,
           const float* __restrict__ b1v, const float* __restrict__ w2,
           const float* __restrict__ b2v, const float* __restrict__ mu,
           const float* __restrict__ sigma, const float* __restrict__ mu_t,
           const float* __restrict__ sigma_t) {
    constexpr int IN = NET ? 29 : 6;
    extern __shared__ float smem[];
    uint32_t* AH = (uint32_t*)(smem + OFF_AH);
    uint32_t* AL = (uint32_t*)(smem + OFF_AL);
    float* Hs  = smem;                 // overlay, used after mainloop only
    float* Xs  = smem + OFF_XS;        // dead after layer0; reused as Rbuf
    float* W0s = smem + OFF_W0;
    float* B0s = smem + OFF_B0;
    float* B1s = smem + OFF_B1;
    float* W2s = smem + OFF_W2;

    const int t = threadIdx.x, lane = t & 31, wid = t >> 5;
    const int e = blockIdx.y;
    const int row0 = blockIdx.x * 64;

    // ---- stage normalized inputs Xs [64 x 33] ----
    for (int q = t; q < 64 * IN; q += NT) {
        int r = q / IN, i = q % IN;
        float v;
        if (NET == 0) {
            int grow = row0 + r, j = grow >> 14, bb = grow & (B_ - 1);
            const float* st = state + ((size_t)e * B_ + bb) * STATE_;
            const float* ac = act + ((size_t)e * B_ + bb) * 8;
            if (i == 0)      v = st[13 + 2 * j];
            else if (i == 1) v = st[21 + 2 * j];
            else if (i == 2) v = st[14 + 2 * j];
            else if (i == 3) v = st[22 + 2 * j];
            else if (i == 4) v = ac[2 * j];
            else             v = ac[2 * j + 1];
        } else {
            int bb = row0 + r;
            if (i < 13) v = state[((size_t)e * B_ + bb) * STATE_ + i];
            else {
                int m = i - 13, j, comp;
                if (m < 8) { j = m >> 1; comp = (m & 1) ? 2 : 0; }
                else       { int m2 = m - 8; j = m2 >> 1; comp = (m2 & 1) ? 3 : 1; }
                v = g_legs_diff[((size_t)e * 4 * B_ + (size_t)j * B_ + bb) * 4 + comp];
            }
        }
        Xs[r * XROW + i] = (v - mu[i]) / (sigma[i] + 1e-8f);
    }
    // ---- stage W0 [IN x 512], biases, packed W2 ----
    for (int q = t; q < IN * 512; q += NT) W0s[q] = w0[(size_t)e * IN * 512 + q];
    if (t < 512) {
        B0s[t] = b0v[(size_t)e * 512 + t];
        B1s[t] = b1v[(size_t)e * 512 + t];
    }
    if (NET == 0) {
        for (int q = t; q < 512 * 4; q += NT) {
            int k = q >> 2, o = q & 3;
            W2s[q] = w2[((size_t)e * 512 + k) * 8 + o];
        }
    } else {
        for (int q = t; q < 512 * 13; q += NT) {
            int k = q / 13, o = q % 13;
            W2s[q] = w2[((size_t)e * 512 + k) * 26 + o];
        }
    }
    __syncthreads();

    // ---- layer0: H[row][k] = relu(X*W0 + b0) written as A fragments ----
    // thread: row = t & 63; q512 = t >> 6 in 0..7: q = q512&3, kh = q512>>2.
    // cols col0 = p*16 + kh*8 + 2q, p = 0..31 (kc = p).
    {
        const int row = t & 63;
        const int q = (t >> 6) & 3;
        const int kh = t >> 8;
        const int mt = row >> 4, rr = row & 15;
        const int g = rr & 7, rh = rr >> 3;
        float xv[IN];
#pragma unroll
        for (int i = 0; i < IN; i++) xv[i] = Xs[row * XROW + i];
#pragma unroll 4
        for (int p = 0; p < 32; p++) {
            const int col0 = p * 16 + kh * 8 + 2 * q;
            float h0 = B0s[col0], h1 = B0s[col0 + 1];
#pragma unroll
            for (int i = 0; i < IN; i++) {
                h0 += xv[i] * W0s[i * 512 + col0];
                h1 += xv[i] * W0s[i * 512 + col0 + 1];
            }
            h0 = fmaxf(h0, 0.f);
            h1 = fmaxf(h1, 0.f);
            float h0h = bfhi(h0), h1h = bfhi(h1);
            const int addr = p * 512 + mt * 128 + (g * 4 + q) * 4 + kh * 2 + rh;
            AH[addr] = packbf(h0, h1);
            AL[addr] = packbf(h0 - h0h, h1 - h1h);
        }
    }
    __syncthreads();

    // ---- layer1: [64 x 512] = A * W1, 3x bf16 split ----
    const int wm = wid & 1;        // m-half: rows wm*32..+31
    const int wn = wid >> 1;       // n-group: cols wn*64..+63
    float acc[2][8][4];
#pragma unroll
    for (int m = 0; m < 2; m++)
#pragma unroll
        for (int n = 0; n < 8; n++)
#pragma unroll
            for (int j = 0; j < 4; j++) acc[m][n][j] = 0.f;

    const uint4* Bw = (const uint4*)(g_B[NET] + (size_t)e * 262144) + (size_t)wn * 8 * 32 * 32;
    for (int kc = 0; kc < 32; kc++) {
        uint4 ah[2], al[2];
#pragma unroll
        for (int mt = 0; mt < 2; mt++) {
            ah[mt] = ((const uint4*)(AH + kc * 512 + (wm * 2 + mt) * 128))[lane];
            al[mt] = ((const uint4*)(AL + kc * 512 + (wm * 2 + mt) * 128))[lane];
        }
#pragma unroll
        for (int ntl = 0; ntl < 8; ntl++) {
            uint4 vb = Bw[(ntl * 32 + kc) * 32 + lane];
#pragma unroll
            for (int mt = 0; mt < 2; mt++) mma16816(acc[mt][ntl], ah[mt], vb.x, vb.y);
#pragma unroll
            for (int mt = 0; mt < 2; mt++) mma16816(acc[mt][ntl], ah[mt], vb.z, vb.w);
#pragma unroll
            for (int mt = 0; mt < 2; mt++) mma16816(acc[mt][ntl], al[mt], vb.x, vb.y);
        }
    }
    __syncthreads();   // A frags dead; Hs overlay becomes safe

    // ---- epilogue: relu(D + b1) -> Hs ----
    {
        const int g = lane >> 2, c = lane & 3;
#pragma unroll
        for (int mt = 0; mt < 2; mt++) {
#pragma unroll
            for (int ntl = 0; ntl < 8; ntl++) {
                const int col = wn * 64 + ntl * 8 + 2 * c;
                const int r1 = (wm * 2 + mt) * 16 + g, r2 = r1 + 8;
                float b0c = B1s[col], b1c = B1s[col + 1];
                float2 v1 = make_float2(fmaxf(acc[mt][ntl][0] + b0c, 0.f),
                                        fmaxf(acc[mt][ntl][1] + b1c, 0.f));
                float2 v2 = make_float2(fmaxf(acc[mt][ntl][2] + b0c, 0.f),
                                        fmaxf(acc[mt][ntl][3] + b1c, 0.f));
                *(float2*)&Hs[r1 * HROW + col] = v1;
                *(float2*)&Hs[r2 * HROW + col] = v2;
            }
        }
    }
    __syncthreads();

    // ---- layer2 + outputs ----
    float* Rbuf = smem + OFF_XS;    // Xs region, dead now
    if (NET == 0) {
        // 64 rows x 4 outs, split k across kh (t>>8): 2 threads per (row,o)
        const int row = t & 63, o = (t >> 6) & 3, kh = t >> 8;
        float s = 0.f;
        const int k0 = kh * 256;
#pragma unroll 8
        for (int k = 0; k < 256; k++) s += Hs[row * HROW + k0 + k] * W2s[(k0 + k) * 4 + o];
        if (kh == 1) Rbuf[row * 4 + o] = s;
        __syncthreads();
        if (kh == 0) {
            float v = s + Rbuf[row * 4 + o] + b2v[(size_t)e * 8 + o];
            g_legs_diff[((size_t)e * 4 * B_ + row0 + row) * 4 + o] =
                v * (sigma_t[o] + 1e-8f) + mu_t[o];
        }
    } else {
        // 64 rows x 13 outs: thread (row = t>>3, q = t&7) does outs {q, q+8(if<13)}
        const int row = t >> 3, q = t & 7;
        const int bb = row0 + row;
        const bool two = (q < 5);
        float s0 = 0.f, s1 = 0.f;
#pragma unroll 4
        for (int k = 0; k < 512; k++) {
            float h = Hs[row * HROW + k];
            s0 += h * W2s[k * 13 + q];
            if (two) s1 += h * W2s[k * 13 + q + 8];
        }
        const float* st = state + ((size_t)e * B_ + bb) * STATE_;
        float* o = g_state_out + ((size_t)e * B_ + bb) * STATE_;
        float v0 = s0 + b2v[(size_t)e * 26 + q];
        o[q] = v0 * (sigma_t[q] + 1e-8f) + mu_t[q] + st[q];
        if (two) {
            int c2 = q + 8;
            float v1 = s1 + b2v[(size_t)e * 26 + c2];
            o[c2] = v1 * (sigma_t[c2] + 1e-8f) + mu_t[c2] + st[c2];
        }
        // leg part of next_state (cols 13..28)
        if (t < 64) {
            int b2i = row0 + t;
            const float* st2 = state + ((size_t)e * B_ + b2i) * STATE_;
            float* o2 = g_state_out + ((size_t)e * B_ + b2i) * STATE_;
#pragma unroll
            for (int j = 0; j < 4; j++) {
                const float* d = g_legs_diff + ((size_t)e * 4 * B_ + (size_t)j * B_ + b2i) * 4;
                o2[13 + 2 * j] = st2[13 + 2 * j] + d[0];
                o2[14 + 2 * j] = st2[14 + 2 * j] + d[2];
                o2[21 + 2 * j] = st2[21 + 2 * j] + d[1];
                o2[22 + 2 * j] = st2[22 + 2 * j] + d[3];
            }
        }
    }
}

// =======================================================================
// Kernel: ensemble mean
// =======================================================================
__global__ void mean_kernel(float* __restrict__ out) {
    const size_t n4 = (size_t)B_ * STATE_ / 4;
    const float4* s0 = (const float4*)g_state_out;
    const float4* s1 = (const float4*)(g_state_out + (size_t)1 * B_ * STATE_);
    const float4* s2 = (const float4*)(g_state_out + (size_t)2 * B_ * STATE_);
    const float4* s3 = (const float4*)(g_state_out + (size_t)3 * B_ * STATE_);
    for (size_t i = blockIdx.x * blockDim.x + threadIdx.x; i < n4;
         i += (size_t)gridDim.x * blockDim.x) {
        float4 a = s0[i], b = s1[i], c = s2[i], d = s3[i];
        float4 r;
        r.x = 0.25f * (a.x + b.x + c.x + d.x);
        r.y = 0.25f * (a.y + b.y + c.y + d.y);
        r.z = 0.25f * (a.z + b.z + c.z + d.z);
        r.w = 0.25f * (a.w + b.w + c.w + d.w);
        ((float4*)out)[i] = r;
    }
}

extern "C" void kernel_launch(void* const* d_in, const int* in_sizes, int n_in,
                              void* d_out, int out_size) {
    const float* state       = (const float*)d_in[0];
    const float* act         = (const float*)d_in[1];
    const float* wl0         = (const float*)d_in[2];
    const float* bl0         = (const float*)d_in[3];
    const float* wl1         = (const float*)d_in[4];
    const float* bl1         = (const float*)d_in[5];
    const float* wl2         = (const float*)d_in[6];
    const float* bl2         = (const float*)d_in[7];
    const float* wp0         = (const float*)d_in[8];
    const float* bp0         = (const float*)d_in[9];
    const float* wp1         = (const float*)d_in[10];
    const float* bp1         = (const float*)d_in[11];
    const float* wp2         = (const float*)d_in[12];
    const float* bp2         = (const float*)d_in[13];
    const float* mu_leg      = (const float*)d_in[14];
    const float* sigma_leg   = (const float*)d_in[15];
    const float* mu_pose     = (const float*)d_in[16];
    const float* sigma_pose  = (const float*)d_in[17];
    const float* mu_t_leg    = (const float*)d_in[18];
    const float* sigma_t_leg = (const float*)d_in[19];
    const float* mu_t_pose   = (const float*)d_in[20];
    const float* sigma_t_pose= (const float*)d_in[21];

    const int smem = SMEM_FLOATS * (int)sizeof(float);   // 229632 B
    cudaFuncSetAttribute(mlp_kernel<0>, cudaFuncAttributeMaxDynamicSharedMemorySize, smem);
    cudaFuncSetAttribute(mlp_kernel<1>, cudaFuncAttributeMaxDynamicSharedMemorySize, smem);

    // 1) pack W1 fragments (bf16 hi/lo)
    prep_kernel<<<2048, 256>>>(wl1, wp1);

    // 2) leg net: (E, 4B) rows -> g_legs_diff
    mlp_kernel<0><<<dim3(1024, E_), NT, smem>>>(state, act, wl0, bl0, bl1, wl2, bl2,
                                                mu_leg, sigma_leg, mu_t_leg, sigma_t_leg);

    // 3) pose net: (E, B) rows -> g_state_out
    mlp_kernel<1><<<dim3(256, E_), NT, smem>>>(state, nullptr, wp0, bp0, bp1, wp2, bp2,
                                               mu_pose, sigma_pose, mu_t_pose, sigma_t_pose);

    // 4) ensemble mean
    mean_kernel<<<256, 256>>>((float*)d_out);
}

// round 17
// speedup vs baseline: 2.1513x; 1.2909x over previous
#include <cuda_runtime.h>
#include <cuda_fp16.h>
#include <cstdint>

// Problem constants
#define E_      4
#define B_      16384
#define STATE_  29
#define HID_    512

// ---------------- SMEM layout (float offsets), TM=64 rows/CTA ----------------
#define OFF_AH  0         // A fp16 frags: 32 kc x 4 mt x 32 lanes x 4 u32 = 16384
#define OFF_XS  16384     // 64 x 33 (padded) = 2112   (dead after layer0)
#define OFF_W0  18496     // W0 [IN x 512]  (<=14848)  (dead after layer0)
#define OFF_B0  33344     // 512 (dead after layer0 -> Rbuf; above Hs end 33280)
#define OFF_B1  33856     // 512 (live in epilogue; above Hs end)
#define OFF_W2  34368     // 512 x NO (<=6656; live in layer2; above Hs end)
#define SMEM_FLOATS 41024 // 164096 bytes
#define HROW 520          // Hs overlays [0, 33280) after mainloop (A frags dead)
#define XROW 33

#define NT 512            // threads per CTA (16 warps -> 4 warps/SMSP)

// ---------------- device scratch ----------------
// Pre-packed W1 fp16 fragments: per (net,e): 64 nt x 32 kc x 32 lanes x {bh0,bh1,bl0,bl1}
__device__ uint32_t g_B[2][(size_t)E_ * 262144];              // 8 MB total
__device__ float g_legs_diff[(size_t)E_ * 4 * B_ * 4];        // (E, 4, B, 4)
__device__ float g_state_out[(size_t)E_ * B_ * STATE_];       // (E, B, 29)

// ---------------- helpers ----------------
__device__ __forceinline__ uint32_t packh(float x, float y) {
    __half2 h = __floats2half2_rn(x, y);   // .x = low 16 bits
    return *reinterpret_cast<uint32_t*>(&h);
}
__device__ __forceinline__ float f16hi(float x) {
    return __half2float(__float2half_rn(x));
}
// mma.sync m16n8k16 row.col f32.f16.f16.f32 (standard PTX, sm_80+)
__device__ __forceinline__ void mma16816(float* d, uint4 a, uint32_t b0, uint32_t b1) {
    asm volatile(
        "mma.sync.aligned.m16n8k16.row.col.f32.f16.f16.f32 "
        "{%0,%1,%2,%3}, {%4,%5,%6,%7}, {%8,%9}, {%0,%1,%2,%3};"
        : "+f"(d[0]), "+f"(d[1]), "+f"(d[2]), "+f"(d[3])
        : "r"(a.x), "r"(a.y), "r"(a.z), "r"(a.w), "r"(b0), "r"(b1));
}

// =======================================================================
// Prep: split W1 into fp16 hi/lo, pack in mma B-fragment register order.
// Per (nt, kc, lane): [bh0, bh1, bl0, bl1] -> one LDG.128 per consumer.
// =======================================================================
__global__ void prep_kernel(const float* __restrict__ wl1, const float* __restrict__ wp1) {
    int idx = blockIdx.x * 256 + threadIdx.x;      // 524288 total
    int l   = idx & 31;
    int kc  = (idx >> 5) & 31;
    int nt  = (idx >> 10) & 63;
    int e   = (idx >> 16) & 3;
    int net = idx >> 18;
    const float* W = (net ? wp1 : wl1) + (size_t)e * 512 * 512;   // [k][n]
    int g = l >> 2, c = l & 3;
    int n  = nt * 8 + g;
    int k0 = kc * 16 + 2 * c;
    float w00 = W[(size_t)k0 * 512 + n];
    float w01 = W[(size_t)(k0 + 1) * 512 + n];
    float w10 = W[(size_t)(k0 + 8) * 512 + n];
    float w11 = W[(size_t)(k0 + 9) * 512 + n];
    float h00 = f16hi(w00), h01 = f16hi(w01), h10 = f16hi(w10), h11 = f16hi(w11);
    uint32_t* dst = g_B[net] + (size_t)e * 262144 + ((size_t)(nt * 32 + kc) * 32 + l) * 4;
    dst[0] = packh(w00, w01);
    dst[1] = packh(w10, w11);
    dst[2] = packh(w00 - h00, w01 - h01);
    dst[3] = packh(w10 - h10, w11 - h11);
}

// =======================================================================
// Fused MLP, TM=64 rows per CTA, 512 threads (16 warps -> 4 warps/SMSP).
// A single fp16 fragment; B split fp16 hi/lo -> 2 MMAs per tile:
//   D = a16*bh + a16*bl  (error ~ 2^-11 from A rounding; << 1e-3)
// Warp (wm = wid&1, wn = wid>>1): rows wm*32..+31, n-cols wn*64..+63.
// =======================================================================
template <int NET>
__global__ void __launch_bounds__(NT, 1)
mlp_kernel(const float* __restrict__ state, const float* __restrict__ act,
           const float* __restrict__ w0, const float* __restrict__ b0v,
           const float* __restrict__ b1v, const float* __restrict__ w2,
           const float* __restrict__ b2v, const float* __restrict__ mu,
           const float* __restrict__ sigma, const float* __restrict__ mu_t,
           const float* __restrict__ sigma_t) {
    constexpr int IN = NET ? 29 : 6;
    extern __shared__ float smem[];
    uint32_t* AH = (uint32_t*)(smem + OFF_AH);
    float* Hs  = smem;                 // overlay, used after mainloop only
    float* Xs  = smem + OFF_XS;
    float* W0s = smem + OFF_W0;
    float* B0s = smem + OFF_B0;
    float* B1s = smem + OFF_B1;
    float* W2s = smem + OFF_W2;

    const int t = threadIdx.x, lane = t & 31, wid = t >> 5;
    const int e = blockIdx.y;
    const int row0 = blockIdx.x * 64;

    // ---- stage normalized inputs Xs [64 x 33] ----
    for (int q = t; q < 64 * IN; q += NT) {
        int r = q / IN, i = q % IN;
        float v;
        if (NET == 0) {
            int grow = row0 + r, j = grow >> 14, bb = grow & (B_ - 1);
            const float* st = state + ((size_t)e * B_ + bb) * STATE_;
            const float* ac = act + ((size_t)e * B_ + bb) * 8;
            if (i == 0)      v = st[13 + 2 * j];
            else if (i == 1) v = st[21 + 2 * j];
            else if (i == 2) v = st[14 + 2 * j];
            else if (i == 3) v = st[22 + 2 * j];
            else if (i == 4) v = ac[2 * j];
            else             v = ac[2 * j + 1];
        } else {
            int bb = row0 + r;
            if (i < 13) v = state[((size_t)e * B_ + bb) * STATE_ + i];
            else {
                int m = i - 13, j, comp;
                if (m < 8) { j = m >> 1; comp = (m & 1) ? 2 : 0; }
                else       { int m2 = m - 8; j = m2 >> 1; comp = (m2 & 1) ? 3 : 1; }
                v = g_legs_diff[((size_t)e * 4 * B_ + (size_t)j * B_ + bb) * 4 + comp];
            }
        }
        Xs[r * XROW + i] = (v - mu[i]) / (sigma[i] + 1e-8f);
    }
    // ---- stage W0 [IN x 512], biases, packed W2 ----
    for (int q = t; q < IN * 512; q += NT) W0s[q] = w0[(size_t)e * IN * 512 + q];
    if (t < 512) {
        B0s[t] = b0v[(size_t)e * 512 + t];
        B1s[t] = b1v[(size_t)e * 512 + t];
    }
    if (NET == 0) {
        for (int q = t; q < 512 * 4; q += NT) {
            int k = q >> 2, o = q & 3;
            W2s[q] = w2[((size_t)e * 512 + k) * 8 + o];
        }
    } else {
        for (int q = t; q < 512 * 13; q += NT) {
            int k = q / 13, o = q % 13;
            W2s[q] = w2[((size_t)e * 512 + k) * 26 + o];
        }
    }
    __syncthreads();

    // ---- layer0: H[row][k] = relu(X*W0 + b0) written as fp16 A fragments ----
    // thread: row = t & 63; q = (t>>6)&3, kh = t>>8; cols p*16 + kh*8 + 2q.
    {
        const int row = t & 63;
        const int q = (t >> 6) & 3;
        const int kh = t >> 8;
        const int mt = row >> 4, rr = row & 15;
        const int g = rr & 7, rh = rr >> 3;
        float xv[IN];
#pragma unroll
        for (int i = 0; i < IN; i++) xv[i] = Xs[row * XROW + i];
#pragma unroll 4
        for (int p = 0; p < 32; p++) {
            const int col0 = p * 16 + kh * 8 + 2 * q;
            float h0 = B0s[col0], h1 = B0s[col0 + 1];
#pragma unroll
            for (int i = 0; i < IN; i++) {
                h0 += xv[i] * W0s[i * 512 + col0];
                h1 += xv[i] * W0s[i * 512 + col0 + 1];
            }
            h0 = fmaxf(h0, 0.f);
            h1 = fmaxf(h1, 0.f);
            const int addr = p * 512 + mt * 128 + (g * 4 + q) * 4 + kh * 2 + rh;
            AH[addr] = packh(h0, h1);
        }
    }
    __syncthreads();

    // ---- layer1: [64 x 512] = A * W1, 2 MMAs per tile (B hi/lo) ----
    const int wm = wid & 1;        // m-half: rows wm*32..+31
    const int wn = wid >> 1;       // n-group: cols wn*64..+63
    float acc[2][8][4];
#pragma unroll
    for (int m = 0; m < 2; m++)
#pragma unroll
        for (int n = 0; n < 8; n++)
#pragma unroll
            for (int j = 0; j < 4; j++) acc[m][n][j] = 0.f;

    const uint4* Bw = (const uint4*)(g_B[NET] + (size_t)e * 262144) + (size_t)wn * 8 * 32 * 32;
    for (int kc = 0; kc < 32; kc++) {
        uint4 ah[2];
#pragma unroll
        for (int mt = 0; mt < 2; mt++)
            ah[mt] = ((const uint4*)(AH + kc * 512 + (wm * 2 + mt) * 128))[lane];
#pragma unroll
        for (int nh = 0; nh < 2; nh++) {
            uint4 vb[4];
#pragma unroll
            for (int j = 0; j < 4; j++)
                vb[j] = Bw[((nh * 4 + j) * 32 + kc) * 32 + lane];
            // hi terms: 8 independent MMAs
#pragma unroll
            for (int j = 0; j < 4; j++) {
                mma16816(acc[0][nh * 4 + j], ah[0], vb[j].x, vb[j].y);
                mma16816(acc[1][nh * 4 + j], ah[1], vb[j].x, vb[j].y);
            }
            // lo terms: dependency distance 8 from matching hi term
#pragma unroll
            for (int j = 0; j < 4; j++) {
                mma16816(acc[0][nh * 4 + j], ah[0], vb[j].z, vb[j].w);
                mma16816(acc[1][nh * 4 + j], ah[1], vb[j].z, vb[j].w);
            }
        }
    }
    __syncthreads();   // A frags dead; Hs overlay becomes safe

    // ---- epilogue: relu(D + b1) -> Hs ----
    {
        const int g = lane >> 2, c = lane & 3;
#pragma unroll
        for (int mt = 0; mt < 2; mt++) {
#pragma unroll
            for (int ntl = 0; ntl < 8; ntl++) {
                const int col = wn * 64 + ntl * 8 + 2 * c;
                const int r1 = (wm * 2 + mt) * 16 + g, r2 = r1 + 8;
                float b0c = B1s[col], b1c = B1s[col + 1];
                float2 v1 = make_float2(fmaxf(acc[mt][ntl][0] + b0c, 0.f),
                                        fmaxf(acc[mt][ntl][1] + b1c, 0.f));
                float2 v2 = make_float2(fmaxf(acc[mt][ntl][2] + b0c, 0.f),
                                        fmaxf(acc[mt][ntl][3] + b1c, 0.f));
                *(float2*)&Hs[r1 * HROW + col] = v1;
                *(float2*)&Hs[r2 * HROW + col] = v2;
            }
        }
    }
    __syncthreads();

    // ---- layer2 + outputs ----
    float* Rbuf = smem + OFF_B0;    // B0s region: dead after layer0, above Hs end
    if (NET == 0) {
        // 64 rows x 4 outs, k split across kh (t>>8): 2 threads per (row,o)
        const int row = t & 63, o = (t >> 6) & 3, kh = t >> 8;
        float s = 0.f;
        const int k0 = kh * 256;
#pragma unroll 8
        for (int k = 0; k < 256; k++) s += Hs[row * HROW + k0 + k] * W2s[(k0 + k) * 4 + o];
        if (kh == 1) Rbuf[row * 4 + o] = s;
        __syncthreads();
        if (kh == 0) {
            float v = s + Rbuf[row * 4 + o] + b2v[(size_t)e * 8 + o];
            g_legs_diff[((size_t)e * 4 * B_ + row0 + row) * 4 + o] =
                v * (sigma_t[o] + 1e-8f) + mu_t[o];
        }
    } else {
        // 64 rows x 13 outs: thread (row = t>>3, q = t&7) does outs {q, q+8(if<13)}
        const int row = t >> 3, q = t & 7;
        const int bb = row0 + row;
        const bool two = (q < 5);
        float s0 = 0.f, s1 = 0.f;
#pragma unroll 4
        for (int k = 0; k < 512; k++) {
            float h = Hs[row * HROW + k];
            s0 += h * W2s[k * 13 + q];
            if (two) s1 += h * W2s[k * 13 + q + 8];
        }
        const float* st = state + ((size_t)e * B_ + bb) * STATE_;
        float* o = g_state_out + ((size_t)e * B_ + bb) * STATE_;
        float v0 = s0 + b2v[(size_t)e * 26 + q];
        o[q] = v0 * (sigma_t[q] + 1e-8f) + mu_t[q] + st[q];
        if (two) {
            int c2 = q + 8;
            float v1 = s1 + b2v[(size_t)e * 26 + c2];
            o[c2] = v1 * (sigma_t[c2] + 1e-8f) + mu_t[c2] + st[c2];
        }
        // leg part of next_state (cols 13..28)
        if (t < 64) {
            int b2i = row0 + t;
            const float* st2 = state + ((size_t)e * B_ + b2i) * STATE_;
            float* o2 = g_state_out + ((size_t)e * B_ + b2i) * STATE_;
#pragma unroll
            for (int j = 0; j < 4; j++) {
                const float* d = g_legs_diff + ((size_t)e * 4 * B_ + (size_t)j * B_ + b2i) * 4;
                o2[13 + 2 * j] = st2[13 + 2 * j] + d[0];
                o2[14 + 2 * j] = st2[14 + 2 * j] + d[2];
                o2[21 + 2 * j] = st2[21 + 2 * j] + d[1];
                o2[22 + 2 * j] = st2[22 + 2 * j] + d[3];
            }
        }
    }
}

// =======================================================================
// Kernel: ensemble mean
// =======================================================================
__global__ void mean_kernel(float* __restrict__ out) {
    const size_t n4 = (size_t)B_ * STATE_ / 4;
    const float4* s0 = (const float4*)g_state_out;
    const float4* s1 = (const float4*)(g_state_out + (size_t)1 * B_ * STATE_);
    const float4* s2 = (const float4*)(g_state_out + (size_t)2 * B_ * STATE_);
    const float4* s3 = (const float4*)(g_state_out + (size_t)3 * B_ * STATE_);
    for (size_t i = blockIdx.x * blockDim.x + threadIdx.x; i < n4;
         i += (size_t)gridDim.x * blockDim.x) {
        float4 a = s0[i], b = s1[i], c = s2[i], d = s3[i];
        float4 r;
        r.x = 0.25f * (a.x + b.x + c.x + d.x);
        r.y = 0.25f * (a.y + b.y + c.y + d.y);
        r.z = 0.25f * (a.z + b.z + c.z + d.z);
        r.w = 0.25f * (a.w + b.w + c.w + d.w);
        ((float4*)out)[i] = r;
    }
}

extern "C" void kernel_launch(void* const* d_in, const int* in_sizes, int n_in,
                              void* d_out, int out_size) {
    const float* state       = (const float*)d_in[0];
    const float* act         = (const float*)d_in[1];
    const float* wl0         = (const float*)d_in[2];
    const float* bl0         = (const float*)d_in[3];
    const float* wl1         = (const float*)d_in[4];
    const float* bl1         = (const float*)d_in[5];
    const float* wl2         = (const float*)d_in[6];
    const float* bl2         = (const float*)d_in[7];
    const float* wp0         = (const float*)d_in[8];
    const float* bp0         = (const float*)d_in[9];
    const float* wp1         = (const float*)d_in[10];
    const float* bp1         = (const float*)d_in[11];
    const float* wp2         = (const float*)d_in[12];
    const float* bp2         = (const float*)d_in[13];
    const float* mu_leg      = (const float*)d_in[14];
    const float* sigma_leg   = (const float*)d_in[15];
    const float* mu_pose     = (const float*)d_in[16];
    const float* sigma_pose  = (const float*)d_in[17];
    const float* mu_t_leg    = (const float*)d_in[18];
    const float* sigma_t_leg = (const float*)d_in[19];
    const float* mu_t_pose   = (const float*)d_in[20];
    const float* sigma_t_pose= (const float*)d_in[21];

    const int smem = SMEM_FLOATS * (int)sizeof(float);   // 164096 B
    cudaFuncSetAttribute(mlp_kernel<0>, cudaFuncAttributeMaxDynamicSharedMemorySize, smem);
    cudaFuncSetAttribute(mlp_kernel<1>, cudaFuncAttributeMaxDynamicSharedMemorySize, smem);

    // 1) pack W1 fragments (fp16 hi/lo)
    prep_kernel<<<2048, 256>>>(wl1, wp1);

    // 2) leg net: (E, 4B) rows -> g_legs_diff
    mlp_kernel<0><<<dim3(1024, E_), NT, smem>>>(state, act, wl0, bl0, bl1, wl2, bl2,
                                                mu_leg, sigma_leg, mu_t_leg, sigma_t_leg);

    // 3) pose net: (E, B) rows -> g_state_out
    mlp_kernel<1><<<dim3(256, E_), NT, smem>>>(state, nullptr, wp0, bp0, bp1, wp2, bp2,
                                               mu_pose, sigma_pose, mu_t_pose, sigma_t_pose);

    // 4) ensemble mean
    mean_kernel<<<256, 256>>>((float*)d_out);
}